// round 14
// baseline (speedup 1.0000x reference)
#include <cuda_runtime.h>
#include <math.h>

#define N_NODES   262144
#define N_EDGES   4194304
#define N_GRAPHS  1024
#define C_IN      16
#define HD        32

// ---------------- scratch (device globals; no allocation allowed) ----------
__device__ __align__(16) float g_agg1[N_NODES * C_IN];   // 16 MB
__device__ __align__(16) float g_h1  [N_NODES * HD];     // 32 MB
__device__ __align__(16) float g_agg2[N_NODES * HD];     // 32 MB
__device__ __align__(16) float g_t   [N_NODES * HD];     // 32 MB
__device__ __align__(16) float g_gate[N_NODES];          // 1 MB

// ---------------- helpers ---------------------------------------------------
__device__ __forceinline__ void red_add_v4(float* addr, float4 v) {
    asm volatile("red.global.add.v4.f32 [%0], {%1,%2,%3,%4};"
                 :: "l"(addr), "f"(v.x), "f"(v.y), "f"(v.z), "f"(v.w)
                 : "memory");
}

#if defined(__CUDA_ARCH__) && (__CUDA_ARCH__ >= 1000)
// packed f32x2 FMA: d = a*b + d (elementwise on both 32-bit halves)
__device__ __forceinline__ void ffma2(unsigned long long& d,
                                      unsigned long long a,
                                      unsigned long long b) {
    asm("fma.rn.f32x2 %0, %1, %2, %0;" : "+l"(d) : "l"(a), "l"(b));
}
#else
// scalar fallback, numerically identical
__device__ __forceinline__ void ffma2(unsigned long long& d,
                                      unsigned long long a,
                                      unsigned long long b) {
    float2 dd = *(float2*)&d;
    float2 aa = *(float2*)&a;
    float2 bb = *(float2*)&b;
    dd.x = fmaf(aa.x, bb.x, dd.x);
    dd.y = fmaf(aa.y, bb.y, dd.y);
    d = *(unsigned long long*)&dd;
}
#endif

__device__ __forceinline__ unsigned long long pack2(float lo, float hi) {
    unsigned long long r;
    asm("mov.b64 %0, {%1, %2};" : "=l"(r) : "f"(lo), "f"(hi));
    return r;
}
__device__ __forceinline__ void unpack2(unsigned long long v, float& lo, float& hi) {
    asm("mov.b64 {%0, %1}, %2;" : "=f"(lo), "=f"(hi) : "l"(v));
}

// 32x32 matvec + bias (+optional relu), weights row-major [c][o] in shared.
// Packed-pair accumulators via fma.rn.f32x2 (FFMA2): 256 FMA issues not 512.
__device__ __forceinline__ void mv32(const float* __restrict__ in,
                                     const float* __restrict__ ws,
                                     const float* __restrict__ bs,
                                     float* __restrict__ out, bool relu) {
    unsigned long long acc[16];
    #pragma unroll
    for (int p = 0; p < 16; p++)
        acc[p] = ((const unsigned long long*)bs)[p];
    #pragma unroll
    for (int c = 0; c < 32; c++) {
        unsigned long long vv = pack2(in[c], in[c]);
        #pragma unroll
        for (int q = 0; q < 8; q++) {
            ulonglong2 w = *(const ulonglong2*)&ws[c * 32 + q * 4]; // LDS.128
            ffma2(acc[q * 2 + 0], vv, w.x);
            ffma2(acc[q * 2 + 1], vv, w.y);
        }
    }
    #pragma unroll
    for (int p = 0; p < 16; p++) {
        float lo, hi;
        unpack2(acc[p], lo, hi);
        if (relu) { lo = fmaxf(lo, 0.f); hi = fmaxf(hi, 0.f); }
        out[p * 2 + 0] = lo;
        out[p * 2 + 1] = hi;
    }
}

// ---------------- kernels ---------------------------------------------------

// K0a/K0b: zero the two scatter accumulators (exact-sized pure STG.128 streams)
__global__ void k_zero1() {
    int i = blockIdx.x * blockDim.x + threadIdx.x;   // grid == N_NODES*C_IN/4
    ((float4*)g_agg1)[i] = make_float4(0.f, 0.f, 0.f, 0.f);
}
__global__ void k_zero2() {
    int i = blockIdx.x * blockDim.x + threadIdx.x;   // grid == N_NODES*HD/4
    ((float4*)g_agg2)[i] = make_float4(0.f, 0.f, 0.f, 0.f);
}

// K1: edge scatter layer 1 (16 floats / edge, 4 threads / edge)
__global__ void __launch_bounds__(256) k_scatter1(
        const float* __restrict__ x, const int* __restrict__ ei) {
    int t = blockIdx.x * blockDim.x + threadIdx.x;
    int e = t >> 2, j = t & 3;
    if (e >= N_EDGES) return;
    int s = __ldg(ei + e);
    int d = __ldg(ei + N_EDGES + e);
    float4 v = __ldg((const float4*)x + ((long long)s * 4 + j));
    red_add_v4(g_agg1 + ((long long)d * C_IN + j * 4), v);
}

// K2: h1 = relu((x + agg1) @ w1 + b1)   (16 -> 32, packed FMA)
__global__ void __launch_bounds__(256) k_node1(const float* __restrict__ x,
                                               const float* __restrict__ w1,
                                               const float* __restrict__ b1) {
    __shared__ __align__(16) float ws[C_IN * HD];
    __shared__ __align__(16) float bs[HD];
    for (int i = threadIdx.x; i < C_IN * HD; i += blockDim.x) ws[i] = w1[i];
    if (threadIdx.x < HD) bs[threadIdx.x] = b1[threadIdx.x];
    __syncthreads();

    int n = blockIdx.x * blockDim.x + threadIdx.x;
    if (n >= N_NODES) return;

    float in[C_IN];
    #pragma unroll
    for (int j = 0; j < 4; j++) {
        float4 a = ((const float4*)x)[n * 4 + j];
        float4 b = ((const float4*)g_agg1)[n * 4 + j];
        in[j * 4 + 0] = a.x + b.x;
        in[j * 4 + 1] = a.y + b.y;
        in[j * 4 + 2] = a.z + b.z;
        in[j * 4 + 3] = a.w + b.w;
    }
    unsigned long long acc[16];
    #pragma unroll
    for (int p = 0; p < 16; p++)
        acc[p] = ((const unsigned long long*)bs)[p];
    #pragma unroll
    for (int c = 0; c < C_IN; c++) {
        unsigned long long vv = pack2(in[c], in[c]);
        #pragma unroll
        for (int q = 0; q < 8; q++) {
            ulonglong2 w = *(const ulonglong2*)&ws[c * 32 + q * 4];
            ffma2(acc[q * 2 + 0], vv, w.x);
            ffma2(acc[q * 2 + 1], vv, w.y);
        }
    }
    #pragma unroll
    for (int q = 0; q < 8; q++) {
        float4 r;
        unpack2(acc[q * 2 + 0], r.x, r.y);
        unpack2(acc[q * 2 + 1], r.z, r.w);
        r.x = fmaxf(r.x, 0.f); r.y = fmaxf(r.y, 0.f);
        r.z = fmaxf(r.z, 0.f); r.w = fmaxf(r.w, 0.f);
        ((float4*)g_h1)[n * 8 + q] = r;
    }
}

// K3: edge scatter layer 2 (32 floats / edge, 8 threads / edge)
__global__ void __launch_bounds__(256) k_scatter2(const int* __restrict__ ei) {
    int t = blockIdx.x * blockDim.x + threadIdx.x;
    int e = t >> 3, j = t & 7;
    if (e >= N_EDGES) return;
    int s = __ldg(ei + e);
    int d = __ldg(ei + N_EDGES + e);
    float4 v = *((const float4*)g_h1 + ((long long)s * 8 + j));
    red_add_v4(g_agg2 + ((long long)d * HD + j * 4), v);
}

// K4: h2 = relu((h1+agg2)@w2+b2); gate MLP -> g_gate; transform MLP -> g_t
__global__ void __launch_bounds__(256) k_node2(
        const float* __restrict__ w2,  const float* __restrict__ b2,
        const float* __restrict__ gw1, const float* __restrict__ gb1,
        const float* __restrict__ gw2, const float* __restrict__ gb2,
        const float* __restrict__ gw3, const float* __restrict__ gb3,
        const float* __restrict__ aw1, const float* __restrict__ ab1,
        const float* __restrict__ aw2, const float* __restrict__ ab2) {
    __shared__ __align__(16) float sw2 [HD * HD];
    __shared__ __align__(16) float sgw1[HD * HD];
    __shared__ __align__(16) float sgw2[HD * HD];
    __shared__ __align__(16) float saw1[HD * HD];
    __shared__ __align__(16) float saw2[HD * HD];
    __shared__ __align__(16) float sgw3[HD];
    __shared__ __align__(16) float sb2[HD], sgb1[HD], sgb2[HD], sab1[HD], sab2[HD];
    __shared__ float sgb3;

    for (int i = threadIdx.x; i < HD * HD; i += blockDim.x) {
        sw2 [i] = w2 [i];
        sgw1[i] = gw1[i];
        sgw2[i] = gw2[i];
        saw1[i] = aw1[i];
        saw2[i] = aw2[i];
    }
    if (threadIdx.x < HD) {
        sgw3[threadIdx.x] = gw3[threadIdx.x];
        sb2 [threadIdx.x] = b2 [threadIdx.x];
        sgb1[threadIdx.x] = gb1[threadIdx.x];
        sgb2[threadIdx.x] = gb2[threadIdx.x];
        sab1[threadIdx.x] = ab1[threadIdx.x];
        sab2[threadIdx.x] = ab2[threadIdx.x];
    }
    if (threadIdx.x == 0) sgb3 = gb3[0];
    __syncthreads();

    int n = blockIdx.x * blockDim.x + threadIdx.x;
    if (n >= N_NODES) return;

    float in[HD];
    #pragma unroll
    for (int j = 0; j < 8; j++) {
        float4 a = ((const float4*)g_h1)[n * 8 + j];
        float4 b = ((const float4*)g_agg2)[n * 8 + j];
        in[j * 4 + 0] = a.x + b.x;
        in[j * 4 + 1] = a.y + b.y;
        in[j * 4 + 2] = a.z + b.z;
        in[j * 4 + 3] = a.w + b.w;
    }

    float h2[HD], tmp[HD];
    mv32(in,  sw2,  sb2,  h2,  true);   // GIN layer 2
    mv32(h2,  sgw1, sgb1, tmp, true);   // gate layer 1
    mv32(tmp, sgw2, sgb2, in,  true);   // gate layer 2 (reuse in[])
    float gate = sgb3;
    #pragma unroll
    for (int c = 0; c < HD; c++) gate = fmaf(in[c], sgw3[c], gate);
    g_gate[n] = gate;

    mv32(h2,  saw1, sab1, tmp, true);   // transform layer 1
    mv32(tmp, saw2, sab2, in,  true);   // transform layer 2
    #pragma unroll
    for (int j = 0; j < 8; j++) {
        float4 r = make_float4(in[j*4+0], in[j*4+1], in[j*4+2], in[j*4+3]);
        ((float4*)g_t)[n * 8 + j] = r;
    }
}

// K5: one block per graph. Binary-search segment bounds in sorted batch_vec,
// block-reduce gate max, accumulate softmax-weighted pool (warp-per-node,
// lane-per-channel, zero atomics), then fused critic MLP on warp 0.
__global__ void __launch_bounds__(256) k_pool_critic(
        const int* __restrict__ batch,
        const float* __restrict__ fw1, const float* __restrict__ fb1,
        const float* __restrict__ fw2, const float* __restrict__ fb2,
        const float* __restrict__ fw3, const float* __restrict__ fb3,
        float* __restrict__ out) {
    const int g = blockIdx.x;
    const int tid = threadIdx.x;
    const int wid = tid >> 5, lane = tid & 31;

    __shared__ int s_lo, s_hi;
    __shared__ float s_max[8];
    __shared__ float s_acc[8][HD];
    __shared__ float s_esum[8];

    if (tid == 0) {
        int lo = 0, hi = N_NODES;
        while (lo < hi) { int m = (lo + hi) >> 1; if (batch[m] < g) lo = m + 1; else hi = m; }
        s_lo = lo;
        int lo2 = lo; hi = N_NODES;
        while (lo2 < hi) { int m = (lo2 + hi) >> 1; if (batch[m] < g + 1) lo2 = m + 1; else hi = m; }
        s_hi = lo2;
    }
    __syncthreads();
    const int lo = s_lo, hi = s_hi;

    // --- pass 1: segment max of gate ---
    float m = -INFINITY;
    for (int i = lo + tid; i < hi; i += 256) m = fmaxf(m, g_gate[i]);
    #pragma unroll
    for (int off = 16; off > 0; off >>= 1)
        m = fmaxf(m, __shfl_xor_sync(0xffffffffu, m, off));
    if (lane == 0) s_max[wid] = m;
    __syncthreads();
    m = s_max[0];
    #pragma unroll
    for (int w = 1; w < 8; w++) m = fmaxf(m, s_max[w]);
    // (empty segment: loops below do nothing; pooled stays 0, matching ref)

    // --- pass 2: acc[ch] = sum e_i * t[i][ch]; esum = sum e_i ---
    float acc = 0.0f, esum = 0.0f;
    for (int i = lo + wid; i < hi; i += 8) {
        float e = expf(g_gate[i] - m);          // per-warp broadcast load
        acc = fmaf(e, g_t[i * HD + lane], acc); // coalesced 128B row
        if (lane == 0) esum += e;
    }
    s_acc[wid][lane] = acc;
    if (lane == 0) s_esum[wid] = esum;
    __syncthreads();

    // --- warp 0: finish pooling + critic MLP ---
    if (wid == 0) {
        float p = 0.0f, den = 0.0f;
        #pragma unroll
        for (int w = 0; w < 8; w++) { p += s_acc[w][lane]; den += s_esum[w]; }
        p /= fmaxf(den, 1e-16f);

        float a = __ldg(&fb1[lane]);
        #pragma unroll
        for (int c = 0; c < HD; c++)
            a = fmaf(__shfl_sync(0xffffffffu, p, c), __ldg(&fw1[c * 32 + lane]), a);
        float a1 = fmaxf(a, 0.f);

        a = __ldg(&fb2[lane]);
        #pragma unroll
        for (int c = 0; c < HD; c++)
            a = fmaf(__shfl_sync(0xffffffffu, a1, c), __ldg(&fw2[c * 32 + lane]), a);
        float a2 = fmaxf(a, 0.f);

        float part = a2 * __ldg(&fw3[lane]);
        #pragma unroll
        for (int off = 16; off > 0; off >>= 1)
            part += __shfl_xor_sync(0xffffffffu, part, off);
        if (lane == 0) out[g] = part + __ldg(&fb3[0]);
    }
}

// ---------------- launch ----------------------------------------------------
extern "C" void kernel_launch(void* const* d_in, const int* in_sizes, int n_in,
                              void* d_out, int out_size) {
    const float* x   = (const float*)d_in[0];
    const float* w1  = (const float*)d_in[1];
    const float* b1  = (const float*)d_in[2];
    const float* w2  = (const float*)d_in[3];
    const float* b2  = (const float*)d_in[4];
    const float* gw1 = (const float*)d_in[5];
    const float* gb1 = (const float*)d_in[6];
    const float* gw2 = (const float*)d_in[7];
    const float* gb2 = (const float*)d_in[8];
    const float* gw3 = (const float*)d_in[9];
    const float* gb3 = (const float*)d_in[10];
    const float* aw1 = (const float*)d_in[11];
    const float* ab1 = (const float*)d_in[12];
    const float* aw2 = (const float*)d_in[13];
    const float* ab2 = (const float*)d_in[14];
    const float* fw1 = (const float*)d_in[15];
    const float* fb1 = (const float*)d_in[16];
    const float* fw2 = (const float*)d_in[17];
    const float* fb2 = (const float*)d_in[18];
    const float* fw3 = (const float*)d_in[19];
    const float* fb3 = (const float*)d_in[20];
    const int*   ei    = (const int*)d_in[21];
    const int*   batch = (const int*)d_in[22];
    float* out = (float*)d_out;

    // K0: zero agg buffers (exact grids, pure store streams)
    k_zero1<<<(N_NODES * C_IN / 4) / 256, 256>>>();
    k_zero2<<<(N_NODES * HD  / 4) / 256, 256>>>();

    // K1: layer-1 edge scatter (4 threads/edge)
    k_scatter1<<<(N_EDGES * 4) / 256, 256>>>(x, ei);

    // K2: GIN layer 1
    k_node1<<<(N_NODES + 255) / 256, 256>>>(x, w1, b1);

    // K3: layer-2 edge scatter (8 threads/edge)
    k_scatter2<<<(N_EDGES * 8) / 256, 256>>>(ei);

    // K4: GIN layer 2 + gate MLP + transform MLP
    k_node2<<<(N_NODES + 255) / 256, 256>>>(w2, b2, gw1, gb1, gw2, gb2,
                                            gw3, gb3, aw1, ab1, aw2, ab2);

    // K5: per-graph softmax pool + critic head (no atomics)
    k_pool_critic<<<N_GRAPHS, 256>>>(batch, fw1, fb1, fw2, fb2, fw3, fb3,
                                     out);
}